// round 3
// baseline (speedup 1.0000x reference)
#include <cuda_runtime.h>
#include <math_constants.h>

#define NROWS 16384
#define DIM   256
#define CSIZE 1024
#define NSTAGE 8

#define BM 128
#define BN 128
#define BK 32
#define TM 8
#define TN 8
#define NBLOCKS (NROWS / BM)   // 128

// Scratch (allocation-free)
__device__ float g_res[NROWS * DIM];
__device__ float g_rownorm[NROWS];
__device__ float g_cbnorm[NSTAGE * CSIZE];
__device__ float g_losspart[NSTAGE * NBLOCKS];

// Copy x -> residual scratch, zero the quant region of d_out.
__global__ void init_kernel(const float* __restrict__ x, float* __restrict__ quant) {
    int i = blockIdx.x * blockDim.x + threadIdx.x;
    int stride = gridDim.x * blockDim.x;
    for (; i < NROWS * DIM; i += stride) {
        g_res[i] = x[i];
        quant[i] = 0.0f;
    }
}

// XLA-style row reduction of sum(v*v) over a 256-long row:
// one warp per row, lane t accumulates strided elements t+32i (FMA chain),
// then butterfly shfl-down tree (16,8,4,2,1).
__device__ __forceinline__ float warp_rownorm(const float* __restrict__ p, int lane) {
    float acc = 0.0f;
#pragma unroll
    for (int i = 0; i < 8; i++) {
        float v = p[lane + 32 * i];
        acc = fmaf(v, v, acc);
    }
#pragma unroll
    for (int off = 16; off > 0; off >>= 1)
        acc += __shfl_down_sync(0xffffffffu, acc, off);
    return acc;
}

// Codeword norms ||cb||^2 for all 8*1024 codewords (one warp per codeword).
__global__ void cbnorm_kernel(const float* __restrict__ codebooks) {
    int row = blockIdx.x * 8 + (threadIdx.x >> 5);
    int lane = threadIdx.x & 31;
    if (row >= NSTAGE * CSIZE) return;
    float s = warp_rownorm(codebooks + (size_t)row * DIM, lane);
    if (lane == 0) g_cbnorm[row] = s;
}

// Per-stage residual row norms (one warp per row).
__global__ void rownorm_kernel() {
    int row = blockIdx.x * 8 + (threadIdx.x >> 5);
    int lane = threadIdx.x & 31;
    float s = warp_rownorm(g_res + (size_t)row * DIM, lane);
    if (lane == 0) g_rownorm[row] = s;
}

// lexicographic (value, index) comparison: true if (v,i) < (w,j)
__device__ __forceinline__ bool lt_vi(float v, int i, float w, int j) {
    return v < w || (v == w && i < j);
}

// Fused per-stage kernel: distance GEMM + argmin (reference-rounding score) +
// residual/quant update + loss partial.
__global__ void __launch_bounds__(256, 1) stage_kernel(
    const float* __restrict__ codebooks,
    float* __restrict__ out,
    int stage)
{
    const float* cb  = codebooks + (size_t)stage * CSIZE * DIM;
    const float* cbn = g_cbnorm + stage * CSIZE;
    float* enc_out = out + 2;                        // [NROWS][NSTAGE] as float
    float* quant   = out + 2 + NROWS * NSTAGE;       // [NROWS][DIM]

    __shared__ float pool[8256];
    float (*As)[BM + 1] = (float (*)[BM + 1])pool;             // 32*129 = 4128
    float (*Bs)[BN + 1] = (float (*)[BN + 1])(pool + 4128);    // 4128
    float* redv  = pool;                  // 2048
    int*   redi  = (int*)(pool + 2048);   // 2048
    int*   enc_s = (int*)(pool + 4096);   // 128
    float* wsum  = pool + 4224;           // 8

    const int tid = threadIdx.x;
    const int tx = tid & 15;           // column group (16)
    const int ty = tid >> 4;           // row group (16)
    const int block_row = blockIdx.x * BM;

    // per-thread argmin state + row norms
    float best[TM], rnv[TM];
    int   bidx[TM];
#pragma unroll
    for (int i = 0; i < TM; i++) {
        best[i] = CUDART_INF_F;
        bidx[i] = 0;
        rnv[i]  = g_rownorm[block_row + ty * TM + i];
    }

    for (int nc = 0; nc < CSIZE; nc += BN) {
        float acc[TM][TN];
#pragma unroll
        for (int i = 0; i < TM; i++)
#pragma unroll
            for (int j = 0; j < TN; j++) acc[i][j] = 0.0f;

        for (int kt = 0; kt < DIM; kt += BK) {
            // Cooperative load + transpose: 1024 float4 each for A and B.
#pragma unroll
            for (int l = 0; l < 4; l++) {
                int idx = tid + l * 256;
                int r  = idx >> 3;
                int c4 = (idx & 7) << 2;
                float4 va = *(const float4*)&g_res[(size_t)(block_row + r) * DIM + kt + c4];
                As[c4 + 0][r] = va.x; As[c4 + 1][r] = va.y;
                As[c4 + 2][r] = va.z; As[c4 + 3][r] = va.w;
                float4 vb = *(const float4*)&cb[(size_t)(nc + r) * DIM + kt + c4];
                Bs[c4 + 0][r] = vb.x; Bs[c4 + 1][r] = vb.y;
                Bs[c4 + 2][r] = vb.z; Bs[c4 + 3][r] = vb.w;
            }
            __syncthreads();
#pragma unroll
            for (int k = 0; k < BK; k++) {
                float a[TM], b[TN];
#pragma unroll
                for (int i = 0; i < TM; i++) a[i] = As[k][ty * TM + i];
#pragma unroll
                for (int j = 0; j < TN; j++) b[j] = Bs[k][tx * TN + j];
#pragma unroll
                for (int i = 0; i < TM; i++)
#pragma unroll
                    for (int j = 0; j < TN; j++)
                        acc[i][j] += a[i] * b[j];   // FFMA chain, k ascending
            }
            __syncthreads();
        }

        // Running argmin with the REFERENCE's score expression and rounding:
        //   d2 = (rn - 2*t) + cn   (two fp32 roundings; 2*t exact)
        // Columns ascending within thread; strict '<' keeps first occurrence.
#pragma unroll
        for (int j = 0; j < TN; j++) {
            int cidx = nc + tx * TN + j;
            float cn = cbn[cidx];
#pragma unroll
            for (int i = 0; i < TM; i++) {
                float score = __fadd_rn(__fsub_rn(rnv[i], 2.0f * acc[i][j]), cn);
                if (score < best[i]) { best[i] = score; bidx[i] = cidx; }
            }
        }
    }

    // Cross-thread (tx) min reduction (red arrays alias As/Bs; all reads done
    // after the final __syncthreads in the k loop).
#pragma unroll
    for (int i = 0; i < TM; i++) {
        int r = ty * TM + i;
        redv[r * 16 + tx] = best[i];
        redi[r * 16 + tx] = bidx[i];
    }
    __syncthreads();
    if (tid < BM) {
        float bv = redv[tid * 16];
        int   bi = redi[tid * 16];
#pragma unroll
        for (int t = 1; t < 16; t++) {
            float v = redv[tid * 16 + t];
            int  ix = redi[tid * 16 + t];
            if (lt_vi(v, ix, bv, bi)) { bv = v; bi = ix; }
        }
        enc_s[tid] = bi;
        enc_out[(size_t)(block_row + tid) * NSTAGE + stage] = (float)bi;
    }
    __syncthreads();

    // Residual update + quant accumulation + loss. 256 threads = 1 dim each.
    float lsum = 0.0f;
    for (int r = 0; r < BM; r++) {
        int c = enc_s[r];
        size_t gi = (size_t)(block_row + r) * DIM + tid;
        float nv = cb[(size_t)c * DIM + tid];
        float rv = g_res[gi];
        float diff = rv - nv;
        g_res[gi] = diff;
        quant[gi] += nv;
        lsum += diff * diff;
    }
#pragma unroll
    for (int o = 16; o > 0; o >>= 1)
        lsum += __shfl_down_sync(0xffffffffu, lsum, o);
    __syncthreads();   // enc_s reads done before wsum aliases pool
    if ((tid & 31) == 0) wsum[tid >> 5] = lsum;
    __syncthreads();
    if (tid == 0) {
        float t = 0.0f;
#pragma unroll
        for (int w = 0; w < 8; w++) t += wsum[w];
        g_losspart[stage * NBLOCKS + blockIdx.x] = t;
    }
}

// Deterministic loss reduction -> out[0], out[1].
__global__ void finalize_kernel(float* __restrict__ out) {
    __shared__ float s[256];
    float t = 0.0f;
    for (int i = threadIdx.x; i < NSTAGE * NBLOCKS; i += 256)
        t += g_losspart[i];
    s[threadIdx.x] = t;
    __syncthreads();
    for (int o = 128; o > 0; o >>= 1) {
        if (threadIdx.x < o) s[threadIdx.x] += s[threadIdx.x + o];
        __syncthreads();
    }
    if (threadIdx.x == 0) {
        float loss = s[0] / (float)((size_t)NROWS * DIM);
        out[0] = loss;   // loss_cd
        out[1] = loss;   // loss_enc (identical by construction)
    }
}

extern "C" void kernel_launch(void* const* d_in, const int* in_sizes, int n_in,
                              void* d_out, int out_size) {
    const float* x         = (const float*)d_in[0];
    const float* codebooks = (const float*)d_in[1];
    float* out = (float*)d_out;

    init_kernel<<<512, 256>>>(x, out + 2 + NROWS * NSTAGE);
    cbnorm_kernel<<<(NSTAGE * CSIZE) / 8, 256>>>(codebooks);
    for (int s = 0; s < NSTAGE; s++) {
        rownorm_kernel<<<NROWS / 8, 256>>>();
        stage_kernel<<<NBLOCKS, 256>>>(codebooks, out, s);
    }
    finalize_kernel<<<1, 256>>>(out);
}

// round 5
// speedup vs baseline: 1.6569x; 1.6569x over previous
#include <cuda_runtime.h>
#include <math_constants.h>
#include <stdint.h>

#define NROWS 16384
#define DIM   256
#define CSIZE 1024
#define NSTAGE 8
#define CAP   16
#define UBLK  2048          // rescreen/update blocks (8 rows each)
#define SPITCH 36           // smem row pitch (words), 32+4: pitch%32==4

// Scratch (allocation-free)
__device__ float g_res[NROWS * DIM];
__device__ float g_rownorm[NROWS];
__device__ float g_cbnorm[NSTAGE * CSIZE];
__device__ int   g_cbmax[NSTAGE];          // float bits (positive)
__device__ int   g_cand[NROWS * CAP];
__device__ int   g_candcnt[NROWS];
__device__ int   g_enc[NROWS];
__device__ float g_losspart[NSTAGE * UBLK];

// ---------- small helpers ----------
__device__ __forceinline__ uint32_t f2tf32(float f) {
    uint32_t r;
    asm("cvt.rna.tf32.f32 %0, %1;" : "=r"(r) : "f"(f));
    return r;
}
__device__ __forceinline__ void mma_tf32(float& c0, float& c1, float& c2, float& c3,
                                         uint32_t a0, uint32_t a1, uint32_t a2, uint32_t a3,
                                         uint32_t b0, uint32_t b1) {
    asm("mma.sync.aligned.m16n8k8.row.col.f32.tf32.tf32.f32 "
        "{%0,%1,%2,%3}, {%4,%5,%6,%7}, {%8,%9}, {%0,%1,%2,%3};"
        : "+f"(c0), "+f"(c1), "+f"(c2), "+f"(c3)
        : "r"(a0), "r"(a1), "r"(a2), "r"(a3), "r"(b0), "r"(b1));
}
// monotonic int key for float (handles negatives; no NaNs here)
__device__ __forceinline__ int fkey(float f) {
    int i = __float_as_int(f);
    return i >= 0 ? i : i ^ 0x7FFFFFFF;
}
__device__ __forceinline__ float funkey(int i) {
    return __int_as_float(i >= 0 ? i : i ^ 0x7FFFFFFF);
}
__device__ __forceinline__ bool lt_vi(float v, int i, float w, int j) {
    return v < w || (v == w && i < j);
}

// ---------- init: x -> res, zero quant, reset cbmax ----------
__global__ void init_kernel(const float* __restrict__ x, float* __restrict__ quant) {
    if (blockIdx.x == 0 && threadIdx.x < NSTAGE) g_cbmax[threadIdx.x] = 0;
    int i = blockIdx.x * blockDim.x + threadIdx.x;
    int stride = gridDim.x * blockDim.x;
    for (; i < NROWS * DIM; i += stride) {
        g_res[i] = x[i];
        quant[i] = 0.0f;
    }
}

// XLA-style row reduction of sum(v*v): lane t sums strided elems t+32i (FMA
// chain, ascending), then shfl-down tree. MUST stay bit-identical everywhere.
__device__ __forceinline__ float warp_rownorm(const float* __restrict__ p, int lane) {
    float acc = 0.0f;
#pragma unroll
    for (int i = 0; i < 8; i++) {
        float v = p[lane + 32 * i];
        acc = fmaf(v, v, acc);
    }
#pragma unroll
    for (int off = 16; off > 0; off >>= 1)
        acc += __shfl_down_sync(0xffffffffu, acc, off);
    return acc;
}

__global__ void cbnorm_kernel(const float* __restrict__ codebooks) {
    int row = blockIdx.x * 8 + (threadIdx.x >> 5);
    int lane = threadIdx.x & 31;
    if (row >= NSTAGE * CSIZE) return;
    float s = warp_rownorm(codebooks + (size_t)row * DIM, lane);
    if (lane == 0) {
        g_cbnorm[row] = s;
        atomicMax(&g_cbmax[row >> 10], __float_as_int(s));  // s > 0
    }
}

__global__ void rownorm_kernel() {
    int row = blockIdx.x * 8 + (threadIdx.x >> 5);
    int lane = threadIdx.x & 31;
    float s = warp_rownorm(g_res + (size_t)row * DIM, lane);
    if (lane == 0) g_rownorm[row] = s;
}

// ---------- screening: tf32 tensor GEMM + sound candidate capture ----------
__global__ void __launch_bounds__(256, 1) screen_kernel(
    const float* __restrict__ codebooks, int stage)
{
    __shared__ uint32_t As[128 * SPITCH];   // res tile   [r][k], tf32 bits
    __shared__ uint32_t Bs[128 * SPITCH];   // cb  tile   [n][k], tf32 bits
    __shared__ int rowmin[128];
    __shared__ int rowcnt[128];
    __shared__ int rowlist[128 * CAP];

    const float* cb  = codebooks + (size_t)stage * CSIZE * DIM;
    const float* cbn = g_cbnorm + stage * CSIZE;

    const int tid  = threadIdx.x;
    const int lane = tid & 31;
    const int wid  = tid >> 5;
    const int wm   = wid >> 2;     // 0..1  (row half, 64 rows)
    const int wn   = wid & 3;      // 0..3  (col group, 32 cols)
    const int g    = lane >> 2;    // 0..7
    const int tg   = lane & 3;     // 0..3
    const int block_row = blockIdx.x * 128;

    if (tid < 128) { rowmin[tid] = 0x7F800000; rowcnt[tid] = 0; }

    const float cbmaxf = __int_as_float(g_cbmax[stage]);
    int   rloc[8];
    float rn8[8], m2[8];
#pragma unroll
    for (int mi = 0; mi < 4; mi++)
#pragma unroll
        for (int h = 0; h < 2; h++) {
            int j = mi * 2 + h;
            int rl = wm * 64 + mi * 16 + g + h * 8;
            rloc[j] = rl;
            float rv = g_rownorm[block_row + rl];
            rn8[j] = rv;
            m2[j] = 2.0f * 0.00390625f * sqrtf(rv * cbmaxf);  // 2 * 2^-8 * sqrt(rn*cnmax)
        }
    __syncthreads();

    for (int nc = 0; nc < CSIZE; nc += 128) {
        float acc[4][4][4];
#pragma unroll
        for (int mi = 0; mi < 4; mi++)
#pragma unroll
            for (int ni = 0; ni < 4; ni++)
#pragma unroll
                for (int e = 0; e < 4; e++) acc[mi][ni][e] = 0.0f;

        for (int kt = 0; kt < DIM; kt += 32) {
            // Stage full 128-row tiles: 4 x 256 float4 per operand.
            float4 va[4], vb[4];
#pragma unroll
            for (int l = 0; l < 4; l++) {
                int idx = tid + l * 256;
                int r  = idx >> 3;
                int c4 = (idx & 7) << 2;
                va[l] = *(const float4*)&g_res[(size_t)(block_row + r) * DIM + kt + c4];
                vb[l] = *(const float4*)&cb[(size_t)(nc + r) * DIM + kt + c4];
            }
            __syncthreads();   // previous chunk's frag reads complete
#pragma unroll
            for (int l = 0; l < 4; l++) {
                int idx = tid + l * 256;
                int r  = idx >> 3;
                int c4 = (idx & 7) << 2;
                uint4 ua = make_uint4(f2tf32(va[l].x), f2tf32(va[l].y), f2tf32(va[l].z), f2tf32(va[l].w));
                uint4 ub = make_uint4(f2tf32(vb[l].x), f2tf32(vb[l].y), f2tf32(vb[l].z), f2tf32(vb[l].w));
                *(uint4*)&As[r * SPITCH + c4] = ua;
                *(uint4*)&Bs[r * SPITCH + c4] = ub;
            }
            __syncthreads();
#pragma unroll
            for (int ks = 0; ks < 4; ks++) {
                const int kb = ks * 8;
                uint32_t a[4][4], b[4][2];
#pragma unroll
                for (int mi = 0; mi < 4; mi++) {
                    int m = wm * 64 + mi * 16 + g;
                    a[mi][0] = As[m * SPITCH + kb + tg];
                    a[mi][1] = As[(m + 8) * SPITCH + kb + tg];
                    a[mi][2] = As[m * SPITCH + kb + tg + 4];
                    a[mi][3] = As[(m + 8) * SPITCH + kb + tg + 4];
                }
#pragma unroll
                for (int ni = 0; ni < 4; ni++) {
                    int n = wn * 32 + ni * 8 + g;
                    b[ni][0] = Bs[n * SPITCH + kb + tg];
                    b[ni][1] = Bs[n * SPITCH + kb + tg + 4];
                }
#pragma unroll
                for (int mi = 0; mi < 4; mi++)
#pragma unroll
                    for (int ni = 0; ni < 4; ni++)
                        mma_tf32(acc[mi][ni][0], acc[mi][ni][1], acc[mi][ni][2], acc[mi][ni][3],
                                 a[mi][0], a[mi][1], a[mi][2], a[mi][3],
                                 b[ni][0], b[ni][1]);
            }
        }

        // approx scores -> per-row running min
        float cnv[4][2];
#pragma unroll
        for (int ni = 0; ni < 4; ni++) {
            int c = nc + wn * 32 + ni * 8 + tg * 2;
            cnv[ni][0] = cbn[c];
            cnv[ni][1] = cbn[c + 1];
        }
        float locmin[8];
#pragma unroll
        for (int j = 0; j < 8; j++) locmin[j] = CUDART_INF_F;
#pragma unroll
        for (int mi = 0; mi < 4; mi++)
#pragma unroll
            for (int ni = 0; ni < 4; ni++)
#pragma unroll
                for (int h = 0; h < 2; h++)
#pragma unroll
                    for (int w = 0; w < 2; w++) {
                        float s = (rn8[mi * 2 + h] - 2.0f * acc[mi][ni][h * 2 + w]) + cnv[ni][w];
                        if (s < locmin[mi * 2 + h]) locmin[mi * 2 + h] = s;
                    }
#pragma unroll
        for (int j = 0; j < 8; j++) atomicMin(&rowmin[rloc[j]], fkey(locmin[j]));
        __syncthreads();

        // capture all candidates within 2*margin of the running min (sound superset)
        float thr[8];
#pragma unroll
        for (int j = 0; j < 8; j++) thr[j] = funkey(rowmin[rloc[j]]) + m2[j];
#pragma unroll
        for (int mi = 0; mi < 4; mi++)
#pragma unroll
            for (int ni = 0; ni < 4; ni++)
#pragma unroll
                for (int h = 0; h < 2; h++)
#pragma unroll
                    for (int w = 0; w < 2; w++) {
                        int j = mi * 2 + h;
                        float s = (rn8[j] - 2.0f * acc[mi][ni][h * 2 + w]) + cnv[ni][w];
                        if (s < thr[j]) {
                            int col = nc + wn * 32 + ni * 8 + tg * 2 + w;
                            int p = atomicAdd(&rowcnt[rloc[j]], 1);
                            if (p < CAP) rowlist[rloc[j] * CAP + p] = col;
                        }
                    }
        __syncthreads();
    }

    if (tid < 128) g_candcnt[block_row + tid] = rowcnt[tid];
    for (int i = tid; i < 128 * CAP; i += 256)
        g_cand[(size_t)block_row * CAP + i] = rowlist[i];
}

// ---------- rescreen: exact reference-rounded scores on candidates ----------
__global__ void rescreen_kernel(const float* __restrict__ codebooks,
                                float* __restrict__ out, int stage)
{
    const float* cb  = codebooks + (size_t)stage * CSIZE * DIM;
    const float* cbn = g_cbnorm + stage * CSIZE;
    float* enc_out = out + 2;

    int row  = blockIdx.x * 8 + (threadIdx.x >> 5);
    int lane = threadIdx.x & 31;
    const float* rrow = &g_res[(size_t)row * DIM];
    float rn = g_rownorm[row];
    int cnt = g_candcnt[row];

    float bestv = CUDART_INF_F;
    int   besti = 0x7FFFFFFF;

    if (cnt <= CAP) {
        if (lane < cnt) {
            int c = g_cand[row * CAP + lane];
            const float* crow = &cb[(size_t)c * DIM];
            float t = 0.0f;
#pragma unroll 8
            for (int k = 0; k < DIM; k++) t = fmaf(rrow[k], crow[k], t);
            bestv = __fadd_rn(__fsub_rn(rn, 2.0f * t), cbn[c]);
            besti = c;
        }
    } else {
        // overflow fallback: exact scan of the whole codebook (rare)
        for (int c = lane; c < CSIZE; c += 32) {
            const float* crow = &cb[(size_t)c * DIM];
            float t = 0.0f;
#pragma unroll 8
            for (int k = 0; k < DIM; k++) t = fmaf(rrow[k], crow[k], t);
            float s = __fadd_rn(__fsub_rn(rn, 2.0f * t), cbn[c]);
            if (lt_vi(s, c, bestv, besti)) { bestv = s; besti = c; }
        }
    }
#pragma unroll
    for (int o = 16; o > 0; o >>= 1) {
        float ov = __shfl_down_sync(0xffffffffu, bestv, o);
        int   oi = __shfl_down_sync(0xffffffffu, besti, o);
        if (lt_vi(ov, oi, bestv, besti)) { bestv = ov; besti = oi; }
    }
    if (lane == 0) {
        g_enc[row] = besti;
        enc_out[(size_t)row * NSTAGE + stage] = (float)besti;
    }
}

// ---------- update: residual, quant, loss, next-stage rownorm ----------
__global__ void update_kernel(const float* __restrict__ codebooks,
                              float* __restrict__ out, int stage)
{
    const float* cb = codebooks + (size_t)stage * CSIZE * DIM;
    float* quant = out + 2 + NROWS * NSTAGE;
    __shared__ float ws[8];

    int row  = blockIdx.x * 8 + (threadIdx.x >> 5);
    int lane = threadIdx.x & 31;
    int c = g_enc[row];
    size_t rb  = (size_t)row * DIM;
    size_t cbb = (size_t)c * DIM;

    float acc = 0.0f;
#pragma unroll
    for (int i = 0; i < 8; i++) {          // strided: d = lane + 32*i (rownorm order!)
        int d = lane + 32 * i;
        float nv = cb[cbb + d];
        float diff = g_res[rb + d] - nv;
        g_res[rb + d] = diff;
        quant[rb + d] += nv;
        acc = fmaf(diff, diff, acc);
    }
#pragma unroll
    for (int o = 16; o > 0; o >>= 1)
        acc += __shfl_down_sync(0xffffffffu, acc, o);
    if (lane == 0) {
        g_rownorm[row] = acc;              // bit-identical to warp_rownorm(res_new)
        ws[threadIdx.x >> 5] = acc;
    }
    __syncthreads();
    if (threadIdx.x == 0) {
        float t = 0.0f;
#pragma unroll
        for (int w = 0; w < 8; w++) t += ws[w];
        g_losspart[stage * UBLK + blockIdx.x] = t;
    }
}

// ---------- loss finalize ----------
__global__ void finalize_kernel(float* __restrict__ out) {
    __shared__ float s[256];
    float t = 0.0f;
    for (int i = threadIdx.x; i < NSTAGE * UBLK; i += 256)
        t += g_losspart[i];
    s[threadIdx.x] = t;
    __syncthreads();
    for (int o = 128; o > 0; o >>= 1) {
        if (threadIdx.x < o) s[threadIdx.x] += s[threadIdx.x + o];
        __syncthreads();
    }
    if (threadIdx.x == 0) {
        float loss = s[0] / (float)((size_t)NROWS * DIM);
        out[0] = loss;
        out[1] = loss;
    }
}

extern "C" void kernel_launch(void* const* d_in, const int* in_sizes, int n_in,
                              void* d_out, int out_size) {
    const float* x         = (const float*)d_in[0];
    const float* codebooks = (const float*)d_in[1];
    float* out = (float*)d_out;

    init_kernel<<<512, 256>>>(x, out + 2 + NROWS * NSTAGE);
    cbnorm_kernel<<<(NSTAGE * CSIZE) / 8, 256>>>(codebooks);
    rownorm_kernel<<<NROWS / 8, 256>>>();
    for (int s = 0; s < NSTAGE; s++) {
        screen_kernel<<<NROWS / 128, 256>>>(codebooks, s);
        rescreen_kernel<<<UBLK, 256>>>(codebooks, out, s);
        update_kernel<<<UBLK, 256>>>(codebooks, out, s);
    }
    finalize_kernel<<<1, 256>>>(out);
}